// round 14
// baseline (speedup 1.0000x reference)
#include <cuda_runtime.h>
#include <cuda_bf16.h>
#include <math.h>
#include <stdint.h>

#define BB 64
#define LL 256
#define EE 512
#define HH 512
#define GG 2048   // 4*H
#define H2 1024   // 2*H
#define ZPAD 80

// ---------------- scratch (device globals; no allocations allowed) -------------
__device__ float g_xg0[LL * BB * GG];
__device__ float g_xg1[LL * BB * GG];
__device__ float g_Hout[BB * LL * H2];           // tf32 bit patterns (valid fp32)
__device__ float g_Hn[BB * LL * H2];
__device__ __nv_bfloat16 g_xb[BB * LL * EE];     // x bf16
__device__ __nv_bfloat16 g_wfB[GG * EE];         // Wih_f bf16
__device__ __nv_bfloat16 g_wbB[GG * EE];         // Wih_b bf16
__device__ uint32_t g_WnT[H2 * H2];              // W_nov transposed, tf32
__device__ uint4 g_hbufb[4 * 2048];              // bf16 fragment-major h per (dir,bg)
__device__ float g_doc[BB * H2];
__device__ float g_D[BB * H2];
__device__ float g_comb[BB * H2];
__device__ unsigned g_cnt[4 * 32];               // init barrier (atomic, replay-safe)
__device__ unsigned g_gen[4 * 32];
__device__ unsigned g_flag[4 * 32 * 32];         // step flags, 128B apart

// ---------------- init barrier (atomicInc, wraps; used once per launch) --------
__device__ __forceinline__ void gsync_grp(int grp) {
    __syncthreads();
    if (threadIdx.x == 0) {
        __threadfence();
        volatile unsigned* gen = &g_gen[grp * 32];
        unsigned old = *gen;
        if (atomicInc(&g_cnt[grp * 32], 31u) == 31u) {
            atomicAdd(&g_gen[grp * 32], 1u);
        } else {
            while (*gen == old) __nanosleep(32);
        }
    }
    __syncthreads();
}

__device__ __forceinline__ float tanha(float x) {
    float r; asm("tanh.approx.f32 %0, %1;" : "=f"(r) : "f"(x)); return r;
}
__device__ __forceinline__ float sigm_fast(float x) {
    return fmaf(tanha(0.5f * x), 0.5f, 0.5f);
}
__device__ __forceinline__ uint32_t f2tf(float f) {
    uint32_t u; asm("cvt.rna.tf32.f32 %0, %1;" : "=r"(u) : "f"(f)); return u;
}
__device__ __forceinline__ void mma_tf32(float* c, const uint32_t* a, const uint32_t* b) {
    asm volatile(
        "mma.sync.aligned.m16n8k8.row.col.f32.tf32.tf32.f32 "
        "{%0,%1,%2,%3}, {%4,%5,%6,%7}, {%8,%9}, {%0,%1,%2,%3};"
        : "+f"(c[0]), "+f"(c[1]), "+f"(c[2]), "+f"(c[3])
        : "r"(a[0]), "r"(a[1]), "r"(a[2]), "r"(a[3]), "r"(b[0]), "r"(b[1]));
}
__device__ __forceinline__ void mma_bf16(float* c, const uint32_t* a, const uint32_t* b) {
    asm volatile(
        "mma.sync.aligned.m16n8k16.row.col.f32.bf16.bf16.f32 "
        "{%0,%1,%2,%3}, {%4,%5,%6,%7}, {%8,%9}, {%0,%1,%2,%3};"
        : "+f"(c[0]), "+f"(c[1]), "+f"(c[2]), "+f"(c[3])
        : "r"(a[0]), "r"(a[1]), "r"(a[2]), "r"(a[3]), "r"(b[0]), "r"(b[1]));
}
__device__ __forceinline__ uint32_t smem_u32(const void* p) {
    uint32_t a;
    asm("{.reg .u64 t; cvta.to.shared.u64 t, %1; cvt.u32.u64 %0, t;}" : "=r"(a) : "l"(p));
    return a;
}
#define CP_ASYNC16(dst, src) \
    asm volatile("cp.async.ca.shared.global [%0], [%1], 16;" :: "r"(dst), "l"(src))
#define CP_ASYNC16_CG(dst, src) \
    asm volatile("cp.async.cg.shared.global [%0], [%1], 16;" :: "r"(dst), "l"(src))
#define CP_COMMIT() asm volatile("cp.async.commit_group;")
#define CP_WAIT(n)  asm volatile("cp.async.wait_group %0;" :: "n"(n))

#define GEMM_SMEM_BYTES (4 * 128 * 36 * 4)    // tf32 gemm dynamic smem (73728)
// recurrent smem: h(32KB) + Whh(64KB) + z + c + bounce(1KB)
#define REC_SMEM_BYTES (2048 * 16 + 4096 * 16 + 32 * ZPAD * 4 + 512 * 4 + 1024)
#define BROW 40   // bf16 gemm smem row stride in bf16 units (80 bytes, conflict-free)

// ---------------- elementwise fp32 -> bf16 (rn) --------------------------------
__global__ void k_cvtb(const float* __restrict__ in, __nv_bfloat16* __restrict__ out, int n4) {
    int i = blockIdx.x * blockDim.x + threadIdx.x;
    if (i < n4) {
        float4 v = ((const float4*)in)[i];
        __nv_bfloat162 lo = __floats2bfloat162_rn(v.x, v.y);
        __nv_bfloat162 hi = __floats2bfloat162_rn(v.z, v.w);
        uint2 o = make_uint2(*(uint32_t*)&lo, *(uint32_t*)&hi);
        ((uint2*)out)[i] = o;
    }
}

// ---------------- bf16 GEMM (m16n8k16), cp.async dbuf, dual-output via z -------
__global__ __launch_bounds__(256, 2) void k_gemm_bf16_dual(
    const __nv_bfloat16* __restrict__ A,
    const __nv_bfloat16* __restrict__ Bt0, const __nv_bfloat16* __restrict__ Bt1,
    const float* __restrict__ bias0, const float* __restrict__ bias1,
    float* __restrict__ C0, float* __restrict__ C1,
    int M, int N, int K)
{
    __shared__ __nv_bfloat16 Asm[2][128 * BROW];
    __shared__ __nv_bfloat16 Bsm[2][128 * BROW];
    const __nv_bfloat16* Bt = blockIdx.z ? Bt1 : Bt0;
    const float* bias = blockIdx.z ? bias1 : bias0;
    float* C = blockIdx.z ? C1 : C0;

    const int tid = threadIdx.x;
    const int lane = tid & 31;
    const int warp = tid >> 5;
    const int wm = warp >> 2;
    const int wn = warp & 3;
    const int g  = lane >> 2;
    const int tg = lane & 3;
    const int bm = blockIdx.y * 128;
    const int bn = blockIdx.x * 128;
    const int srow = tid >> 2;
    const int sc   = (tid & 3) * 8;

    const uint32_t as_base = smem_u32(&Asm[0][0]);
    const uint32_t bs_base = smem_u32(&Bsm[0][0]);
    const uint32_t soff = (srow * BROW + sc) * 2;
    const uint32_t rstep = 64 * BROW * 2;
    const uint32_t bufstep = 128 * BROW * 2;

    float acc[4][4][4];
#pragma unroll
    for (int i = 0; i < 4; i++)
#pragma unroll
        for (int j = 0; j < 4; j++)
#pragma unroll
            for (int e = 0; e < 4; e++) acc[i][j][e] = 0.f;

    const int ntiles = K >> 5;

#pragma unroll
    for (int r = 0; r < 2; r++) {
        int row = srow + 64 * r;
        CP_ASYNC16(as_base + soff + r * rstep, A + (size_t)(bm + row) * K + sc);
        CP_ASYNC16(bs_base + soff + r * rstep, Bt + (size_t)(bn + row) * K + sc);
    }
    CP_COMMIT();

    for (int kt = 0; kt < ntiles; kt++) {
        const int buf = kt & 1;
        if (kt + 1 < ntiles) {
            const int k0n = (kt + 1) << 5;
            const uint32_t bofs = (buf ^ 1) * bufstep;
#pragma unroll
            for (int r = 0; r < 2; r++) {
                int row = srow + 64 * r;
                CP_ASYNC16(as_base + bofs + soff + r * rstep, A + (size_t)(bm + row) * K + k0n + sc);
                CP_ASYNC16(bs_base + bofs + soff + r * rstep, Bt + (size_t)(bn + row) * K + k0n + sc);
            }
            CP_COMMIT();
            CP_WAIT(1);
        } else {
            CP_WAIT(0);
        }
        __syncthreads();

        const __nv_bfloat16* Ab = Asm[buf];
        const __nv_bfloat16* Bb = Bsm[buf];
#pragma unroll
        for (int kk = 0; kk < 2; kk++) {
            const int kc = kk * 16;
            uint32_t a[4][4], b[4][2];
#pragma unroll
            for (int i = 0; i < 4; i++) {
                int r0 = wm * 64 + i * 16 + g;
                a[i][0] = *(const uint32_t*)&Ab[r0 * BROW + kc + 2 * tg];
                a[i][1] = *(const uint32_t*)&Ab[(r0 + 8) * BROW + kc + 2 * tg];
                a[i][2] = *(const uint32_t*)&Ab[r0 * BROW + kc + 8 + 2 * tg];
                a[i][3] = *(const uint32_t*)&Ab[(r0 + 8) * BROW + kc + 8 + 2 * tg];
            }
#pragma unroll
            for (int j = 0; j < 4; j++) {
                int n0 = wn * 32 + j * 8 + g;
                b[j][0] = *(const uint32_t*)&Bb[n0 * BROW + kc + 2 * tg];
                b[j][1] = *(const uint32_t*)&Bb[n0 * BROW + kc + 8 + 2 * tg];
            }
#pragma unroll
            for (int i = 0; i < 4; i++)
#pragma unroll
                for (int j = 0; j < 4; j++) mma_bf16(acc[i][j], a[i], b[j]);
        }
        __syncthreads();
    }
#pragma unroll
    for (int i = 0; i < 4; i++) {
#pragma unroll
        for (int j = 0; j < 4; j++) {
            int col = bn + wn * 32 + j * 8 + tg * 2;
            float bv0 = bias[col];
            float bv1 = bias[col + 1];
            int m0 = bm + wm * 64 + i * 16 + g;
            int m1 = m0 + 8;
            int r0 = (m0 & (LL - 1)) * BB + (m0 >> 8);   // REMAP
            int r1 = (m1 & (LL - 1)) * BB + (m1 >> 8);
            *(float2*)(C + (size_t)r0 * N + col) = make_float2(acc[i][j][0] + bv0, acc[i][j][1] + bv1);
            *(float2*)(C + (size_t)r1 * N + col) = make_float2(acc[i][j][2] + bv0, acc[i][j][3] + bv1);
        }
    }
}

// ---------------- tf32 GEMM (novelty), cp.async double-buffer (R9-validated) ---
template <bool REMAP>
__global__ __launch_bounds__(256, 2) void k_gemm_tf32(
    const uint32_t* __restrict__ A, const uint32_t* __restrict__ Bt,
    const float* __restrict__ bias, float* __restrict__ C,
    int M, int N, int K)
{
    extern __shared__ uint32_t smg[];
    uint32_t* Asm = smg;
    uint32_t* Bsm = smg + 2 * 128 * 36;
    const int tid = threadIdx.x;
    const int lane = tid & 31;
    const int warp = tid >> 5;
    const int wm = warp >> 2;
    const int wn = warp & 3;
    const int g  = lane >> 2;
    const int tg = lane & 3;
    const int bm = blockIdx.y * 128;
    const int bn = blockIdx.x * 128;
    const int srow = tid >> 3;
    const int scol = (tid & 7) << 2;

    const uint32_t as_base = smem_u32(Asm);
    const uint32_t bs_base = smem_u32(Bsm);
    const uint32_t soff = (srow * 36 + scol) * 4;

    float acc[4][4][4];
#pragma unroll
    for (int i = 0; i < 4; i++)
#pragma unroll
        for (int j = 0; j < 4; j++)
#pragma unroll
            for (int e = 0; e < 4; e++) acc[i][j][e] = 0.f;

    const int ntiles = K >> 5;

#pragma unroll
    for (int r = 0; r < 4; r++) {
        int row = srow + 32 * r;
        CP_ASYNC16(as_base + soff + r * (32 * 36 * 4), A + (size_t)(bm + row) * K + scol);
        CP_ASYNC16(bs_base + soff + r * (32 * 36 * 4), Bt + (size_t)(bn + row) * K + scol);
    }
    CP_COMMIT();

    for (int kt = 0; kt < ntiles; kt++) {
        const int buf = kt & 1;
        if (kt + 1 < ntiles) {
            const int k0n = (kt + 1) << 5;
            const uint32_t bofs = (buf ^ 1) * (128 * 36 * 4);
#pragma unroll
            for (int r = 0; r < 4; r++) {
                int row = srow + 32 * r;
                CP_ASYNC16(as_base + bofs + soff + r * (32 * 36 * 4), A + (size_t)(bm + row) * K + k0n + scol);
                CP_ASYNC16(bs_base + bofs + soff + r * (32 * 36 * 4), Bt + (size_t)(bn + row) * K + k0n + scol);
            }
            CP_COMMIT();
            CP_WAIT(1);
        } else {
            CP_WAIT(0);
        }
        __syncthreads();

        const uint32_t* Ab = Asm + buf * (128 * 36);
        const uint32_t* Bb = Bsm + buf * (128 * 36);
#pragma unroll
        for (int kk = 0; kk < 32; kk += 8) {
            uint32_t a[4][4], b[4][2];
#pragma unroll
            for (int i = 0; i < 4; i++) {
                int base = wm * 64 + i * 16;
                a[i][0] = Ab[(base + g)     * 36 + kk + tg];
                a[i][1] = Ab[(base + g + 8) * 36 + kk + tg];
                a[i][2] = Ab[(base + g)     * 36 + kk + tg + 4];
                a[i][3] = Ab[(base + g + 8) * 36 + kk + tg + 4];
            }
#pragma unroll
            for (int j = 0; j < 4; j++) {
                int nb = wn * 32 + j * 8;
                b[j][0] = Bb[(nb + g) * 36 + kk + tg];
                b[j][1] = Bb[(nb + g) * 36 + kk + tg + 4];
            }
#pragma unroll
            for (int i = 0; i < 4; i++)
#pragma unroll
                for (int j = 0; j < 4; j++) mma_tf32(acc[i][j], a[i], b[j]);
        }
        __syncthreads();
    }
#pragma unroll
    for (int i = 0; i < 4; i++) {
#pragma unroll
        for (int j = 0; j < 4; j++) {
            int col = bn + wn * 32 + j * 8 + tg * 2;
            float bv0 = bias ? bias[col] : 0.f;
            float bv1 = bias ? bias[col + 1] : 0.f;
            int m0 = bm + wm * 64 + i * 16 + g;
            int m1 = m0 + 8;
            int r0 = REMAP ? ((m0 & (LL - 1)) * BB + (m0 >> 8)) : m0;
            int r1 = REMAP ? ((m1 & (LL - 1)) * BB + (m1 >> 8)) : m1;
            *(float2*)(C + (size_t)r0 * N + col) = make_float2(acc[i][j][0] + bv0, acc[i][j][1] + bv1);
            *(float2*)(C + (size_t)r1 * N + col) = make_float2(acc[i][j][2] + bv0, acc[i][j][3] + bv1);
        }
    }
}

// ---------------- 1024x1024 transpose, fp32 -> tf32 bits ------------------------
__global__ void k_transpose(const float* __restrict__ in, uint32_t* __restrict__ out) {
    __shared__ float t[32][33];
    int bx = blockIdx.x * 32, by = blockIdx.y * 32;
    int x = threadIdx.x, y = threadIdx.y;
#pragma unroll
    for (int j = 0; j < 32; j += 8) t[y + j][x] = in[(size_t)(by + y + j) * H2 + bx + x];
    __syncthreads();
#pragma unroll
    for (int j = 0; j < 32; j += 8) out[(size_t)(bx + y + j) * H2 + by + x] = f2tf(t[x][y + j]);
}

// ---------------- persistent bidirectional LSTM, bf16 mma ----------------------
// h slice per CTA is 64 contiguous uint4 (kk == useg) -> coalesced writeback via
// a persistent 1KB smem bounce buffer.
__global__ __launch_bounds__(256, 1) void k_recurrent(
    const float* __restrict__ Whh_f, const float* __restrict__ Whh_b,
    const int* __restrict__ slen, const int* __restrict__ dlen,
    const float* __restrict__ xg0, const float* __restrict__ xg1,
    uint4* __restrict__ hb, float* __restrict__ Hout, float* __restrict__ doc)
{
    extern __shared__ float sm[];
    uint4* s_hb4 = (uint4*)sm;                   // 2048 uint4 (32KB)
    uint4* s_wb4 = (uint4*)sm + 2048;            // [wn 4][kk 32][lane 32] (64KB)
    float* s_z = sm + (2048 + 4096) * 4;         // [32][ZPAD]
    float* s_c = s_z + 32 * ZPAD;                // [512]
    uint4* s_bn4 = (uint4*)(s_c + 512);          // bounce: 64 uint4 (1KB)
    __nv_bfloat16* s_bnh = (__nv_bfloat16*)s_bn4;

    const int tid = threadIdx.x;
    const int lane = tid & 31;
    const int warp = tid >> 5;
    const int wm = warp >> 2;
    const int wn = warp & 3;
    const int g  = lane >> 2;
    const int tg = lane & 3;
    const int dir = blockIdx.x >> 6;
    const int bg  = (blockIdx.x >> 5) & 1;
    const int useg = blockIdx.x & 31;
    const int hu0 = useg * 16;
    const int grp = blockIdx.x >> 5;
    const int cta = blockIdx.x & 31;
    const float* Whh = dir ? Whh_b : Whh_f;
    const float* xg  = dir ? xg1 : xg0;
    uint4* hperm = hb + (dir * 2 + bg) * 2048;

    if (tid == 0) g_flag[grp * 1024 + cta * 32] = 0u;

    // one-time: pack Whh fragments as bf16 [wn][kk][lane] uint4
    uint32_t* s_ww = (uint32_t*)s_wb4;
    for (int w = tid; w < 16384; w += 256) {
        int comp = w & 3;
        int l    = (w >> 2) & 31;
        int kk   = (w >> 7) & 31;
        int wn_  = w >> 12;
        int j   = comp >> 1;
        int khi = comp & 1;
        int n = wn_ * 16 + j * 8 + (l >> 2);
        int k = kk * 16 + khi * 8 + (l & 3) * 2;
        int gate = n >> 4, unit = hu0 + (n & 15);
        const float* wr = Whh + (size_t)(gate * HH + unit) * HH + k;
        __nv_bfloat162 p = __floats2bfloat162_rn(wr[0], wr[1]);
        s_ww[w] = *(uint32_t*)&p;
    }
    for (int i = tid; i < 512; i += 256) s_c[i] = 0.f;
    if (tid < 64) s_bn4[tid] = make_uint4(0u, 0u, 0u, 0u);    // bf16 zeros

    int lofs[2], bidx[2], huv[2];
    __nv_bfloat16* hpw = (__nv_bfloat16*)hperm;
#pragma unroll
    for (int half = 0; half < 2; half++) {
        int idx = tid + half * 256;
        int bl = idx >> 4, u = idx & 15;
        int hu = hu0 + u;
        int q = bl >> 4, rr = bl & 15;
        int kk = hu >> 4, km = hu & 15;           // kk == useg
        int u4i = (kk * 2 + q) * 32 + (rr & 7) * 4 + ((km & 7) >> 1);
        int comp = (rr >> 3) + 2 * (km >> 3);
        int pofs = u4i * 8 + comp * 2 + (km & 1);
        lofs[half] = pofs - useg * 512;           // local index into bounce (0..1023)
        bidx[half] = bg * 32 + bl;
        huv[half]  = hu;
        hpw[pofs] = __float2bfloat16(0.f);        // zero-init global slice
    }
    gsync_grp(grp);

    const int sl0 = slen[bidx[0]];
    const int sl1 = slen[bidx[1]];
    const int dl0 = dlen[bidx[0]];
    const int dl1 = dlen[bidx[1]];
    float docacc[2] = {0.f, 0.f};

    const uint4* awp = s_hb4 + wm * 32 + lane;
    const uint4* bwp = s_wb4 + (wn * 32) * 32 + lane;
    const uint4* hsrc4 = (const uint4*)hperm;
    const uint32_t hb_base = smem_u32(s_hb4);

    for (int step = 0; step < LL; ++step) {
        const int t = dir ? (LL - 1 - step) : step;

        // stage h block via cp.async first (latency starts earliest)
#pragma unroll
        for (int r = 0; r < 8; r++) {
            int i = tid + r * 256;
            CP_ASYNC16_CG(hb_base + i * 16, hsrc4 + i);
        }
        CP_COMMIT();

        // prefetch xg for both halves (overlaps with cp.async in flight)
        float x0[4], x1[4];
        {
            const float* xp0 = xg + ((size_t)t * BB + bidx[0]) * GG + huv[0];
            x0[0] = xp0[0]; x0[1] = xp0[HH]; x0[2] = xp0[2 * HH]; x0[3] = xp0[3 * HH];
            const float* xp1 = xg + ((size_t)t * BB + bidx[1]) * GG + huv[1];
            x1[0] = xp1[0]; x1[1] = xp1[HH]; x1[2] = xp1[2 * HH]; x1[3] = xp1[3 * HH];
        }

        CP_WAIT(0);
        __syncthreads();

        float acc0[4] = {0.f, 0.f, 0.f, 0.f};
        float acc1[4] = {0.f, 0.f, 0.f, 0.f};
#pragma unroll 8
        for (int kk = 0; kk < 32; kk++) {
            uint4 a4 = awp[kk * 64];
            uint4 b4 = bwp[kk * 32];
            uint32_t b0[2] = {b4.x, b4.y};
            uint32_t b1[2] = {b4.z, b4.w};
            mma_bf16(acc0, (const uint32_t*)&a4, b0);
            mma_bf16(acc1, (const uint32_t*)&a4, b1);
        }
        {
            int zr = wm * 16 + g;
            int zc = wn * 16 + tg * 2;
            *(float2*)&s_z[zr * ZPAD + zc]           = make_float2(acc0[0], acc0[1]);
            *(float2*)&s_z[(zr + 8) * ZPAD + zc]     = make_float2(acc0[2], acc0[3]);
            *(float2*)&s_z[zr * ZPAD + zc + 8]       = make_float2(acc1[0], acc1[1]);
            *(float2*)&s_z[(zr + 8) * ZPAD + zc + 8] = make_float2(acc1[2], acc1[3]);
        }
        __syncthreads();

        // gates: write h updates into the smem bounce buffer (conditional on act)
#pragma unroll
        for (int half = 0; half < 2; half++) {
            int idx = tid + half * 256;
            int bl = idx >> 4, u = idx & 15;
            int b = bidx[half];
            const float* xv = half ? x1 : x0;
            float zi = s_z[bl * ZPAD + u]      + xv[0];
            float zf = s_z[bl * ZPAD + 16 + u] + xv[1];
            float zg = s_z[bl * ZPAD + 32 + u] + xv[2];
            float zo = s_z[bl * ZPAD + 48 + u] + xv[3];
            float c  = s_c[idx];
            float cn = sigm_fast(zf) * c + sigm_fast(zi) * tanha(zg);
            float hn = sigm_fast(zo) * tanha(cn);
            bool act = t < (half ? sl1 : sl0);
            if (act) {
                s_c[idx] = cn;
                s_bnh[lofs[half]] = __float2bfloat16(hn);
            }
            Hout[(size_t)(b * LL + t) * H2 + dir * HH + huv[half]] =
                act ? __uint_as_float(f2tf(hn)) : 0.f;
            if (t < (half ? dl1 : dl0)) docacc[half] += (act ? hn : 0.f);
        }

        // coalesced writeback of our 1KB slice, then arrive + wait
        __syncthreads();
        if (tid < 64) hperm[useg * 64 + tid] = s_bn4[tid];
        __syncthreads();
        if (tid == 0) {
            __threadfence();
            atomicExch(&g_flag[grp * 1024 + cta * 32], (unsigned)step + 1u);
        }
        if (tid < 32) {
            const volatile unsigned* fl = &g_flag[grp * 1024];
            unsigned tgt = (unsigned)step + 1u;
            while (fl[tid * 32] < tgt) __nanosleep(16);
        }
        __syncthreads();
    }

#pragma unroll
    for (int half = 0; half < 2; half++) {
        float inv = 1.f / (float)(half ? dl1 : dl0);
        doc[bidx[half] * H2 + dir * HH + huv[half]] = docacc[half] * inv;
    }
}

// ---------------- epilogue -----------------------------------------------------
__global__ void k_mv(const float* __restrict__ W, const float* __restrict__ v,
                     const float* __restrict__ bias, float* __restrict__ out)
{
    int b = blockIdx.y;
    int wid = threadIdx.x >> 5, lane = threadIdx.x & 31;
    int d = blockIdx.x * 8 + wid;
    const float4* wp = (const float4*)(W + (size_t)d * H2);
    const float4* vp = (const float4*)(v + (size_t)b * H2);
    float acc = 0.f;
    for (int e = lane; e < H2 / 4; e += 32) {
        float4 a = wp[e], c = vp[e];
        acc += a.x * c.x + a.y * c.y + a.z * c.z + a.w * c.w;
    }
#pragma unroll
    for (int off = 16; off > 0; off >>= 1) acc += __shfl_down_sync(0xffffffffu, acc, off);
    if (lane == 0) out[b * H2 + d] = acc + (bias ? bias[d] : 0.f);
}

// sequential scan; 1 warp per batch; both Hn and Hout prefetched one step ahead
__global__ __launch_bounds__(32) void k_scan(
    const float* __restrict__ Hout, const float* __restrict__ Hn,
    const float* __restrict__ comb, const float* __restrict__ pos,
    const float* __restrict__ b_con, const float* __restrict__ b_sal,
    const float* __restrict__ b_nov,
    const float* __restrict__ w_cls, const float* __restrict__ b_cls,
    float* __restrict__ out)
{
    int b = blockIdx.x, lane = threadIdx.x;
    float4 s4[8], c4[8];
    const float4* combB = (const float4*)(comb + (size_t)b * H2);
#pragma unroll
    for (int j = 0; j < 8; j++) {
        s4[j] = make_float4(0.f, 0.f, 0.f, 0.f);
        c4[j] = combB[lane * 8 + j];
    }
    float wcls = w_cls[0], bcls = b_cls[0], bnov = b_nov[0];
    float bconst = b_con[0] + b_sal[0];
    const float4* HnB = (const float4*)(Hn + (size_t)b * LL * H2);
    const float4* HoB = (const float4*)(Hout + (size_t)b * LL * H2);

    float4 nhn[8], nho[8];
#pragma unroll
    for (int j = 0; j < 8; j++) {
        nhn[j] = HnB[lane * 8 + j];
        nho[j] = HoB[lane * 8 + j];
    }

    for (int i = 0; i < LL; i++) {
        float4 hn_c[8], ho_c[8];
#pragma unroll
        for (int j = 0; j < 8; j++) { hn_c[j] = nhn[j]; ho_c[j] = nho[j]; }
        if (i + 1 < LL) {
#pragma unroll
            for (int j = 0; j < 8; j++) {
                nhn[j] = HnB[(size_t)(i + 1) * 256 + lane * 8 + j];
                nho[j] = HoB[(size_t)(i + 1) * 256 + lane * 8 + j];
            }
        }

        float pn = 0.f, pb = 0.f;
#pragma unroll
        for (int j = 0; j < 8; j++) {
            pn += hn_c[j].x * s4[j].x + hn_c[j].y * s4[j].y + hn_c[j].z * s4[j].z + hn_c[j].w * s4[j].w;
            pb += ho_c[j].x * c4[j].x + ho_c[j].y * c4[j].y + ho_c[j].z * c4[j].z + ho_c[j].w * c4[j].w;
        }
#pragma unroll
        for (int off = 16; off > 0; off >>= 1) {
            pn += __shfl_xor_sync(0xffffffffu, pn, off);
            pb += __shfl_xor_sync(0xffffffffu, pb, off);
        }
        float base = pb + bconst + pos[i];
        float nov = (i == 0) ? 0.f : (pn + bnov);
        float p = sigm_fast(wcls * (base + nov) + bcls);
#pragma unroll
        for (int j = 0; j < 8; j++) {
            s4[j].x += ho_c[j].x * p; s4[j].y += ho_c[j].y * p;
            s4[j].z += ho_c[j].z * p; s4[j].w += ho_c[j].w * p;
        }
        if (lane == 0) out[b * LL + i] = p;
    }
}

// ---------------- launch --------------------------------------------------------
extern "C" void kernel_launch(void* const* d_in, const int* in_sizes, int n_in,
                              void* d_out, int out_size)
{
    (void)in_sizes; (void)n_in; (void)out_size;
    const float* x     = (const float*)d_in[0];
    const int*   slen  = (const int*)  d_in[1];
    const int*   dlen  = (const int*)  d_in[2];
    const float* Wih_f = (const float*)d_in[3];
    const float* Whh_f = (const float*)d_in[4];
    const float* b_f   = (const float*)d_in[5];
    const float* Wih_b = (const float*)d_in[6];
    const float* Whh_b = (const float*)d_in[7];
    const float* b_b   = (const float*)d_in[8];
    const float* W_doc = (const float*)d_in[9];
    const float* b_doc = (const float*)d_in[10];
    const float* w_con = (const float*)d_in[11];
    const float* b_con = (const float*)d_in[12];
    const float* W_sal = (const float*)d_in[13];
    const float* b_sal = (const float*)d_in[14];
    const float* W_nov = (const float*)d_in[15];
    const float* b_nov = (const float*)d_in[16];
    const float* pos   = (const float*)d_in[17];
    const float* w_cls = (const float*)d_in[18];
    const float* b_cls = (const float*)d_in[19];
    float* out = (float*)d_out;

    float *p_xg0, *p_xg1, *p_Hout, *p_Hn, *p_doc, *p_D, *p_comb;
    __nv_bfloat16 *p_xb, *p_wfB, *p_wbB;
    uint32_t *p_WnT;
    uint4 *p_hb;
    cudaGetSymbolAddress((void**)&p_xg0,  g_xg0);
    cudaGetSymbolAddress((void**)&p_xg1,  g_xg1);
    cudaGetSymbolAddress((void**)&p_Hout, g_Hout);
    cudaGetSymbolAddress((void**)&p_Hn,   g_Hn);
    cudaGetSymbolAddress((void**)&p_xb,   g_xb);
    cudaGetSymbolAddress((void**)&p_wfB,  g_wfB);
    cudaGetSymbolAddress((void**)&p_wbB,  g_wbB);
    cudaGetSymbolAddress((void**)&p_WnT,  g_WnT);
    cudaGetSymbolAddress((void**)&p_hb,   g_hbufb);
    cudaGetSymbolAddress((void**)&p_doc,  g_doc);
    cudaGetSymbolAddress((void**)&p_D,    g_D);
    cudaGetSymbolAddress((void**)&p_comb, g_comb);

    const int M = BB * LL;

    cudaFuncSetAttribute(k_gemm_tf32<false>, cudaFuncAttributeMaxDynamicSharedMemorySize, GEMM_SMEM_BYTES);

    // prep: convert xg-GEMM operands to bf16; W_nov to tf32 transposed
    k_cvtb<<<(M * EE / 4 + 255) / 256, 256>>>(x, p_xb, M * EE / 4);
    k_cvtb<<<(GG * EE / 4 + 255) / 256, 256>>>(Wih_f, p_wfB, GG * EE / 4);
    k_cvtb<<<(GG * EE / 4 + 255) / 256, 256>>>(Wih_b, p_wbB, GG * EE / 4);
    k_transpose<<<dim3(32, 32), dim3(32, 8)>>>(W_nov, p_WnT);

    // both input projections in ONE launch (z selects direction)
    k_gemm_bf16_dual<<<dim3(GG / 128, M / 128, 2), 256>>>(
        p_xb, p_wfB, p_wbB, b_f, b_b, p_xg0, p_xg1, M, GG, EE);

    cudaFuncSetAttribute(k_recurrent, cudaFuncAttributeMaxDynamicSharedMemorySize, REC_SMEM_BYTES);
    k_recurrent<<<128, 256, REC_SMEM_BYTES>>>(Whh_f, Whh_b, slen, dlen,
                                              p_xg0, p_xg1, p_hb, p_Hout, p_doc);

    // D = W_doc . doc + b_doc ; comb = W_sal . D + w_con
    k_mv<<<dim3(H2 / 8, BB), 256>>>(W_doc, p_doc, b_doc, p_D);
    k_mv<<<dim3(H2 / 8, BB), 256>>>(W_sal, p_D, w_con, p_comb);

    // novelty GEMM stays tf32 (feeds output scores directly)
    k_gemm_tf32<false><<<dim3(H2 / 128, M / 128), 256, GEMM_SMEM_BYTES>>>((const uint32_t*)p_Hout, p_WnT, nullptr, p_Hn, M, H2, H2);

    k_scan<<<BB, 32>>>(p_Hout, p_Hn, p_comb, pos, b_con, b_sal, b_nov, w_cls, b_cls, out);
}

// round 15
// speedup vs baseline: 1.0703x; 1.0703x over previous
#include <cuda_runtime.h>
#include <cuda_bf16.h>
#include <math.h>
#include <stdint.h>

#define BB 64
#define LL 256
#define EE 512
#define HH 512
#define GG 2048   // 4*H
#define H2 1024   // 2*H
#define ZPAD 80

// ---------------- scratch (device globals; no allocations allowed) -------------
__device__ float g_xg0[LL * BB * GG];
__device__ float g_xg1[LL * BB * GG];
__device__ float g_Hout[BB * LL * H2];           // tf32 bit patterns (valid fp32)
__device__ float g_Hn[BB * LL * H2];
__device__ __nv_bfloat16 g_xb[BB * LL * EE];     // x bf16
__device__ __nv_bfloat16 g_wfB[GG * EE];         // Wih_f bf16
__device__ __nv_bfloat16 g_wbB[GG * EE];         // Wih_b bf16
__device__ uint32_t g_WnT[H2 * H2];              // W_nov transposed, tf32
__device__ uint4 g_hbufb[4 * 2048];              // bf16 fragment-major h per (dir,bg)
__device__ float g_doc[BB * H2];
__device__ float g_D[BB * H2];
__device__ float g_comb[BB * H2];
__device__ unsigned g_cnt[4 * 32];               // init barrier (atomic, replay-safe)
__device__ unsigned g_gen[4 * 32];
__device__ unsigned g_flag[4 * 32 * 32];         // step flags, 128B apart

// ---------------- init barrier (atomicInc, wraps; used once per launch) --------
__device__ __forceinline__ void gsync_grp(int grp) {
    __syncthreads();
    if (threadIdx.x == 0) {
        __threadfence();
        volatile unsigned* gen = &g_gen[grp * 32];
        unsigned old = *gen;
        if (atomicInc(&g_cnt[grp * 32], 31u) == 31u) {
            atomicAdd(&g_gen[grp * 32], 1u);
        } else {
            while (*gen == old) __nanosleep(32);
        }
    }
    __syncthreads();
}

// ---------------- per-step flag barrier (R12-validated) -------------------------
__device__ __forceinline__ void gsync_flag(int grp, int cta, unsigned tgt) {
    __syncthreads();
    if (threadIdx.x == 0) {
        __threadfence();
        atomicExch(&g_flag[grp * 1024 + cta * 32], tgt);
    }
    if (threadIdx.x < 32) {
        const volatile unsigned* fl = &g_flag[grp * 1024];
        while (fl[threadIdx.x * 32] < tgt) __nanosleep(16);
    }
    __syncthreads();
}

__device__ __forceinline__ float tanha(float x) {
    float r; asm("tanh.approx.f32 %0, %1;" : "=f"(r) : "f"(x)); return r;
}
__device__ __forceinline__ float sigm_fast(float x) {
    return fmaf(tanha(0.5f * x), 0.5f, 0.5f);
}
__device__ __forceinline__ uint32_t f2tf(float f) {
    uint32_t u; asm("cvt.rna.tf32.f32 %0, %1;" : "=r"(u) : "f"(f)); return u;
}
__device__ __forceinline__ void mma_tf32(float* c, const uint32_t* a, const uint32_t* b) {
    asm volatile(
        "mma.sync.aligned.m16n8k8.row.col.f32.tf32.tf32.f32 "
        "{%0,%1,%2,%3}, {%4,%5,%6,%7}, {%8,%9}, {%0,%1,%2,%3};"
        : "+f"(c[0]), "+f"(c[1]), "+f"(c[2]), "+f"(c[3])
        : "r"(a[0]), "r"(a[1]), "r"(a[2]), "r"(a[3]), "r"(b[0]), "r"(b[1]));
}
__device__ __forceinline__ void mma_bf16(float* c, const uint32_t* a, const uint32_t* b) {
    asm volatile(
        "mma.sync.aligned.m16n8k16.row.col.f32.bf16.bf16.f32 "
        "{%0,%1,%2,%3}, {%4,%5,%6,%7}, {%8,%9}, {%0,%1,%2,%3};"
        : "+f"(c[0]), "+f"(c[1]), "+f"(c[2]), "+f"(c[3])
        : "r"(a[0]), "r"(a[1]), "r"(a[2]), "r"(a[3]), "r"(b[0]), "r"(b[1]));
}
__device__ __forceinline__ uint32_t smem_u32(const void* p) {
    uint32_t a;
    asm("{.reg .u64 t; cvta.to.shared.u64 t, %1; cvt.u32.u64 %0, t;}" : "=r"(a) : "l"(p));
    return a;
}
#define CP_ASYNC16(dst, src) \
    asm volatile("cp.async.ca.shared.global [%0], [%1], 16;" :: "r"(dst), "l"(src))
#define CP_ASYNC16_CG(dst, src) \
    asm volatile("cp.async.cg.shared.global [%0], [%1], 16;" :: "r"(dst), "l"(src))
#define CP_COMMIT() asm volatile("cp.async.commit_group;")
#define CP_WAIT(n)  asm volatile("cp.async.wait_group %0;" :: "n"(n))

#define GEMM_SMEM_BYTES (4 * 128 * 36 * 4)    // tf32 gemm dynamic smem (73728)
#define REC_SMEM_BYTES (2048 * 16 + 4096 * 16 + 32 * ZPAD * 4 + 512 * 4)  // 110592
#define BROW 40   // bf16 gemm smem row stride in bf16 units (80 bytes, conflict-free)

// ---------------- elementwise fp32 -> bf16 (rn) --------------------------------
__global__ void k_cvtb(const float* __restrict__ in, __nv_bfloat16* __restrict__ out, int n4) {
    int i = blockIdx.x * blockDim.x + threadIdx.x;
    if (i < n4) {
        float4 v = ((const float4*)in)[i];
        __nv_bfloat162 lo = __floats2bfloat162_rn(v.x, v.y);
        __nv_bfloat162 hi = __floats2bfloat162_rn(v.z, v.w);
        uint2 o = make_uint2(*(uint32_t*)&lo, *(uint32_t*)&hi);
        ((uint2*)out)[i] = o;
    }
}

// ---------------- bf16 GEMM (m16n8k16), cp.async dbuf, dual-output via z -------
__global__ __launch_bounds__(256, 2) void k_gemm_bf16_dual(
    const __nv_bfloat16* __restrict__ A,
    const __nv_bfloat16* __restrict__ Bt0, const __nv_bfloat16* __restrict__ Bt1,
    const float* __restrict__ bias0, const float* __restrict__ bias1,
    float* __restrict__ C0, float* __restrict__ C1,
    int M, int N, int K)
{
    __shared__ __nv_bfloat16 Asm[2][128 * BROW];
    __shared__ __nv_bfloat16 Bsm[2][128 * BROW];
    const __nv_bfloat16* Bt = blockIdx.z ? Bt1 : Bt0;
    const float* bias = blockIdx.z ? bias1 : bias0;
    float* C = blockIdx.z ? C1 : C0;

    const int tid = threadIdx.x;
    const int lane = tid & 31;
    const int warp = tid >> 5;
    const int wm = warp >> 2;
    const int wn = warp & 3;
    const int g  = lane >> 2;
    const int tg = lane & 3;
    const int bm = blockIdx.y * 128;
    const int bn = blockIdx.x * 128;
    const int srow = tid >> 2;
    const int sc   = (tid & 3) * 8;

    const uint32_t as_base = smem_u32(&Asm[0][0]);
    const uint32_t bs_base = smem_u32(&Bsm[0][0]);
    const uint32_t soff = (srow * BROW + sc) * 2;
    const uint32_t rstep = 64 * BROW * 2;
    const uint32_t bufstep = 128 * BROW * 2;

    float acc[4][4][4];
#pragma unroll
    for (int i = 0; i < 4; i++)
#pragma unroll
        for (int j = 0; j < 4; j++)
#pragma unroll
            for (int e = 0; e < 4; e++) acc[i][j][e] = 0.f;

    const int ntiles = K >> 5;

#pragma unroll
    for (int r = 0; r < 2; r++) {
        int row = srow + 64 * r;
        CP_ASYNC16(as_base + soff + r * rstep, A + (size_t)(bm + row) * K + sc);
        CP_ASYNC16(bs_base + soff + r * rstep, Bt + (size_t)(bn + row) * K + sc);
    }
    CP_COMMIT();

    for (int kt = 0; kt < ntiles; kt++) {
        const int buf = kt & 1;
        if (kt + 1 < ntiles) {
            const int k0n = (kt + 1) << 5;
            const uint32_t bofs = (buf ^ 1) * bufstep;
#pragma unroll
            for (int r = 0; r < 2; r++) {
                int row = srow + 64 * r;
                CP_ASYNC16(as_base + bofs + soff + r * rstep, A + (size_t)(bm + row) * K + k0n + sc);
                CP_ASYNC16(bs_base + bofs + soff + r * rstep, Bt + (size_t)(bn + row) * K + k0n + sc);
            }
            CP_COMMIT();
            CP_WAIT(1);
        } else {
            CP_WAIT(0);
        }
        __syncthreads();

        const __nv_bfloat16* Ab = Asm[buf];
        const __nv_bfloat16* Bb = Bsm[buf];
#pragma unroll
        for (int kk = 0; kk < 2; kk++) {
            const int kc = kk * 16;
            uint32_t a[4][4], b[4][2];
#pragma unroll
            for (int i = 0; i < 4; i++) {
                int r0 = wm * 64 + i * 16 + g;
                a[i][0] = *(const uint32_t*)&Ab[r0 * BROW + kc + 2 * tg];
                a[i][1] = *(const uint32_t*)&Ab[(r0 + 8) * BROW + kc + 2 * tg];
                a[i][2] = *(const uint32_t*)&Ab[r0 * BROW + kc + 8 + 2 * tg];
                a[i][3] = *(const uint32_t*)&Ab[(r0 + 8) * BROW + kc + 8 + 2 * tg];
            }
#pragma unroll
            for (int j = 0; j < 4; j++) {
                int n0 = wn * 32 + j * 8 + g;
                b[j][0] = *(const uint32_t*)&Bb[n0 * BROW + kc + 2 * tg];
                b[j][1] = *(const uint32_t*)&Bb[n0 * BROW + kc + 8 + 2 * tg];
            }
#pragma unroll
            for (int i = 0; i < 4; i++)
#pragma unroll
                for (int j = 0; j < 4; j++) mma_bf16(acc[i][j], a[i], b[j]);
        }
        __syncthreads();
    }
#pragma unroll
    for (int i = 0; i < 4; i++) {
#pragma unroll
        for (int j = 0; j < 4; j++) {
            int col = bn + wn * 32 + j * 8 + tg * 2;
            float bv0 = bias[col];
            float bv1 = bias[col + 1];
            int m0 = bm + wm * 64 + i * 16 + g;
            int m1 = m0 + 8;
            int r0 = (m0 & (LL - 1)) * BB + (m0 >> 8);   // REMAP
            int r1 = (m1 & (LL - 1)) * BB + (m1 >> 8);
            *(float2*)(C + (size_t)r0 * N + col) = make_float2(acc[i][j][0] + bv0, acc[i][j][1] + bv1);
            *(float2*)(C + (size_t)r1 * N + col) = make_float2(acc[i][j][2] + bv0, acc[i][j][3] + bv1);
        }
    }
}

// ---------------- tf32 GEMM (novelty), cp.async double-buffer (R9-validated) ---
template <bool REMAP>
__global__ __launch_bounds__(256, 2) void k_gemm_tf32(
    const uint32_t* __restrict__ A, const uint32_t* __restrict__ Bt,
    const float* __restrict__ bias, float* __restrict__ C,
    int M, int N, int K)
{
    extern __shared__ uint32_t smg[];
    uint32_t* Asm = smg;
    uint32_t* Bsm = smg + 2 * 128 * 36;
    const int tid = threadIdx.x;
    const int lane = tid & 31;
    const int warp = tid >> 5;
    const int wm = warp >> 2;
    const int wn = warp & 3;
    const int g  = lane >> 2;
    const int tg = lane & 3;
    const int bm = blockIdx.y * 128;
    const int bn = blockIdx.x * 128;
    const int srow = tid >> 3;
    const int scol = (tid & 7) << 2;

    const uint32_t as_base = smem_u32(Asm);
    const uint32_t bs_base = smem_u32(Bsm);
    const uint32_t soff = (srow * 36 + scol) * 4;

    float acc[4][4][4];
#pragma unroll
    for (int i = 0; i < 4; i++)
#pragma unroll
        for (int j = 0; j < 4; j++)
#pragma unroll
            for (int e = 0; e < 4; e++) acc[i][j][e] = 0.f;

    const int ntiles = K >> 5;

#pragma unroll
    for (int r = 0; r < 4; r++) {
        int row = srow + 32 * r;
        CP_ASYNC16(as_base + soff + r * (32 * 36 * 4), A + (size_t)(bm + row) * K + scol);
        CP_ASYNC16(bs_base + soff + r * (32 * 36 * 4), Bt + (size_t)(bn + row) * K + scol);
    }
    CP_COMMIT();

    for (int kt = 0; kt < ntiles; kt++) {
        const int buf = kt & 1;
        if (kt + 1 < ntiles) {
            const int k0n = (kt + 1) << 5;
            const uint32_t bofs = (buf ^ 1) * (128 * 36 * 4);
#pragma unroll
            for (int r = 0; r < 4; r++) {
                int row = srow + 32 * r;
                CP_ASYNC16(as_base + bofs + soff + r * (32 * 36 * 4), A + (size_t)(bm + row) * K + k0n + scol);
                CP_ASYNC16(bs_base + bofs + soff + r * (32 * 36 * 4), Bt + (size_t)(bn + row) * K + k0n + scol);
            }
            CP_COMMIT();
            CP_WAIT(1);
        } else {
            CP_WAIT(0);
        }
        __syncthreads();

        const uint32_t* Ab = Asm + buf * (128 * 36);
        const uint32_t* Bb = Bsm + buf * (128 * 36);
#pragma unroll
        for (int kk = 0; kk < 32; kk += 8) {
            uint32_t a[4][4], b[4][2];
#pragma unroll
            for (int i = 0; i < 4; i++) {
                int base = wm * 64 + i * 16;
                a[i][0] = Ab[(base + g)     * 36 + kk + tg];
                a[i][1] = Ab[(base + g + 8) * 36 + kk + tg];
                a[i][2] = Ab[(base + g)     * 36 + kk + tg + 4];
                a[i][3] = Ab[(base + g + 8) * 36 + kk + tg + 4];
            }
#pragma unroll
            for (int j = 0; j < 4; j++) {
                int nb = wn * 32 + j * 8;
                b[j][0] = Bb[(nb + g) * 36 + kk + tg];
                b[j][1] = Bb[(nb + g) * 36 + kk + tg + 4];
            }
#pragma unroll
            for (int i = 0; i < 4; i++)
#pragma unroll
                for (int j = 0; j < 4; j++) mma_tf32(acc[i][j], a[i], b[j]);
        }
        __syncthreads();
    }
#pragma unroll
    for (int i = 0; i < 4; i++) {
#pragma unroll
        for (int j = 0; j < 4; j++) {
            int col = bn + wn * 32 + j * 8 + tg * 2;
            float bv0 = bias ? bias[col] : 0.f;
            float bv1 = bias ? bias[col + 1] : 0.f;
            int m0 = bm + wm * 64 + i * 16 + g;
            int m1 = m0 + 8;
            int r0 = REMAP ? ((m0 & (LL - 1)) * BB + (m0 >> 8)) : m0;
            int r1 = REMAP ? ((m1 & (LL - 1)) * BB + (m1 >> 8)) : m1;
            *(float2*)(C + (size_t)r0 * N + col) = make_float2(acc[i][j][0] + bv0, acc[i][j][1] + bv1);
            *(float2*)(C + (size_t)r1 * N + col) = make_float2(acc[i][j][2] + bv0, acc[i][j][3] + bv1);
        }
    }
}

// ---------------- 1024x1024 transpose, fp32 -> tf32 bits ------------------------
__global__ void k_transpose(const float* __restrict__ in, uint32_t* __restrict__ out) {
    __shared__ float t[32][33];
    int bx = blockIdx.x * 32, by = blockIdx.y * 32;
    int x = threadIdx.x, y = threadIdx.y;
#pragma unroll
    for (int j = 0; j < 32; j += 8) t[y + j][x] = in[(size_t)(by + y + j) * H2 + bx + x];
    __syncthreads();
#pragma unroll
    for (int j = 0; j < 32; j += 8) out[(size_t)(bx + y + j) * H2 + by + x] = f2tf(t[x][y + j]);
}

// ---------------- persistent bidirectional LSTM, bf16 mma ----------------------
// R12 structure + loop-invariant Whh fragments hoisted into registers (128 regs).
__global__ __launch_bounds__(256, 1) void k_recurrent(
    const float* __restrict__ Whh_f, const float* __restrict__ Whh_b,
    const int* __restrict__ slen, const int* __restrict__ dlen,
    const float* __restrict__ xg0, const float* __restrict__ xg1,
    uint4* __restrict__ hb, float* __restrict__ Hout, float* __restrict__ doc)
{
    extern __shared__ float sm[];
    uint4* s_hb4 = (uint4*)sm;                   // 2048 uint4 (32KB)
    uint4* s_wb4 = (uint4*)sm + 2048;            // [wn 4][kk 32][lane 32] (64KB), pack staging
    float* s_z = sm + (2048 + 4096) * 4;         // [32][ZPAD]
    float* s_c = s_z + 32 * ZPAD;                // [512]

    const int tid = threadIdx.x;
    const int lane = tid & 31;
    const int warp = tid >> 5;
    const int wm = warp >> 2;
    const int wn = warp & 3;
    const int g  = lane >> 2;
    const int tg = lane & 3;
    const int dir = blockIdx.x >> 6;
    const int bg  = (blockIdx.x >> 5) & 1;
    const int useg = blockIdx.x & 31;
    const int hu0 = useg * 16;
    const int grp = blockIdx.x >> 5;
    const int cta = blockIdx.x & 31;
    const float* Whh = dir ? Whh_b : Whh_f;
    const float* xg  = dir ? xg1 : xg0;
    uint4* hperm = hb + (dir * 2 + bg) * 2048;

    if (tid == 0) g_flag[grp * 1024 + cta * 32] = 0u;

    // one-time: pack Whh fragments as bf16 [wn][kk][lane] uint4 (validated mapping)
    uint32_t* s_ww = (uint32_t*)s_wb4;
    for (int w = tid; w < 16384; w += 256) {
        int comp = w & 3;
        int l    = (w >> 2) & 31;
        int kk   = (w >> 7) & 31;
        int wn_  = w >> 12;
        int j   = comp >> 1;
        int khi = comp & 1;
        int n = wn_ * 16 + j * 8 + (l >> 2);
        int k = kk * 16 + khi * 8 + (l & 3) * 2;
        int gate = n >> 4, unit = hu0 + (n & 15);
        const float* wr = Whh + (size_t)(gate * HH + unit) * HH + k;
        __nv_bfloat162 p = __floats2bfloat162_rn(wr[0], wr[1]);
        s_ww[w] = *(uint32_t*)&p;
    }
    for (int i = tid; i < 512; i += 256) s_c[i] = 0.f;

    int pofs[2], bidx[2], huv[2];
    __nv_bfloat16* hpw = (__nv_bfloat16*)hperm;
#pragma unroll
    for (int half = 0; half < 2; half++) {
        int idx = tid + half * 256;
        int bl = idx >> 4, u = idx & 15;
        int hu = hu0 + u;
        int q = bl >> 4, rr = bl & 15;
        int kk = hu >> 4, km = hu & 15;
        int u4i = (kk * 2 + q) * 32 + (rr & 7) * 4 + ((km & 7) >> 1);
        int comp = (rr >> 3) + 2 * (km >> 3);
        pofs[half] = u4i * 8 + comp * 2 + (km & 1);
        bidx[half] = bg * 32 + bl;
        huv[half]  = hu;
        hpw[pofs[half]] = __float2bfloat16(0.f);
    }
    __syncthreads();

    // hoist this thread's Whh fragments into registers (loop-invariant)
    const uint4* bwp = s_wb4 + (wn * 32) * 32 + lane;
    uint4 b_reg[32];
#pragma unroll
    for (int kk = 0; kk < 32; kk++) b_reg[kk] = bwp[kk * 32];

    gsync_grp(grp);

    const int sl0 = slen[bidx[0]];
    const int sl1 = slen[bidx[1]];
    const int dl0 = dlen[bidx[0]];
    const int dl1 = dlen[bidx[1]];
    float docacc[2] = {0.f, 0.f};

    const uint4* awp = s_hb4 + wm * 32 + lane;
    const uint4* hsrc4 = (const uint4*)hperm;
    const uint32_t hb_base = smem_u32(s_hb4);

    for (int step = 0; step < LL; ++step) {
        const int t = dir ? (LL - 1 - step) : step;

        // stage h block via cp.async first (latency starts earliest)
#pragma unroll
        for (int r = 0; r < 8; r++) {
            int i = tid + r * 256;
            CP_ASYNC16_CG(hb_base + i * 16, hsrc4 + i);
        }
        CP_COMMIT();

        // prefetch xg for both halves (overlaps with cp.async in flight)
        float x0[4], x1[4];
        {
            const float* xp0 = xg + ((size_t)t * BB + bidx[0]) * GG + huv[0];
            x0[0] = xp0[0]; x0[1] = xp0[HH]; x0[2] = xp0[2 * HH]; x0[3] = xp0[3 * HH];
            const float* xp1 = xg + ((size_t)t * BB + bidx[1]) * GG + huv[1];
            x1[0] = xp1[0]; x1[1] = xp1[HH]; x1[2] = xp1[2 * HH]; x1[3] = xp1[3 * HH];
        }

        CP_WAIT(0);
        __syncthreads();

        float acc0[4] = {0.f, 0.f, 0.f, 0.f};
        float acc1[4] = {0.f, 0.f, 0.f, 0.f};
#pragma unroll
        for (int kk = 0; kk < 32; kk++) {
            uint4 a4 = awp[kk * 64];
            uint32_t b0[2] = {b_reg[kk].x, b_reg[kk].y};
            uint32_t b1[2] = {b_reg[kk].z, b_reg[kk].w};
            mma_bf16(acc0, (const uint32_t*)&a4, b0);
            mma_bf16(acc1, (const uint32_t*)&a4, b1);
        }
        {
            int zr = wm * 16 + g;
            int zc = wn * 16 + tg * 2;
            *(float2*)&s_z[zr * ZPAD + zc]           = make_float2(acc0[0], acc0[1]);
            *(float2*)&s_z[(zr + 8) * ZPAD + zc]     = make_float2(acc0[2], acc0[3]);
            *(float2*)&s_z[zr * ZPAD + zc + 8]       = make_float2(acc1[0], acc1[1]);
            *(float2*)&s_z[(zr + 8) * ZPAD + zc + 8] = make_float2(acc1[2], acc1[3]);
        }
        __syncthreads();

#pragma unroll
        for (int half = 0; half < 2; half++) {
            int idx = tid + half * 256;
            int bl = idx >> 4, u = idx & 15;
            int b = bidx[half];
            const float* xv = half ? x1 : x0;
            float zi = s_z[bl * ZPAD + u]      + xv[0];
            float zf = s_z[bl * ZPAD + 16 + u] + xv[1];
            float zg = s_z[bl * ZPAD + 32 + u] + xv[2];
            float zo = s_z[bl * ZPAD + 48 + u] + xv[3];
            float c  = s_c[idx];
            float cn = sigm_fast(zf) * c + sigm_fast(zi) * tanha(zg);
            float hn = sigm_fast(zo) * tanha(cn);
            bool act = t < (half ? sl1 : sl0);
            if (act) {
                s_c[idx] = cn;
                hpw[pofs[half]] = __float2bfloat16(hn);
            }
            Hout[(size_t)(b * LL + t) * H2 + dir * HH + huv[half]] =
                act ? __uint_as_float(f2tf(hn)) : 0.f;
            if (t < (half ? dl1 : dl0)) docacc[half] += (act ? hn : 0.f);
        }
        gsync_flag(grp, cta, (unsigned)step + 1u);
    }

#pragma unroll
    for (int half = 0; half < 2; half++) {
        float inv = 1.f / (float)(half ? dl1 : dl0);
        doc[bidx[half] * H2 + dir * HH + huv[half]] = docacc[half] * inv;
    }
}

// ---------------- epilogue -----------------------------------------------------
__global__ void k_mv(const float* __restrict__ W, const float* __restrict__ v,
                     const float* __restrict__ bias, float* __restrict__ out)
{
    int b = blockIdx.y;
    int wid = threadIdx.x >> 5, lane = threadIdx.x & 31;
    int d = blockIdx.x * 8 + wid;
    const float4* wp = (const float4*)(W + (size_t)d * H2);
    const float4* vp = (const float4*)(v + (size_t)b * H2);
    float acc = 0.f;
    for (int e = lane; e < H2 / 4; e += 32) {
        float4 a = wp[e], c = vp[e];
        acc += a.x * c.x + a.y * c.y + a.z * c.z + a.w * c.w;
    }
#pragma unroll
    for (int off = 16; off > 0; off >>= 1) acc += __shfl_down_sync(0xffffffffu, acc, off);
    if (lane == 0) out[b * H2 + d] = acc + (bias ? bias[d] : 0.f);
}

// sequential scan; 1 warp per batch; both Hn and Hout prefetched one step ahead
__global__ __launch_bounds__(32) void k_scan(
    const float* __restrict__ Hout, const float* __restrict__ Hn,
    const float* __restrict__ comb, const float* __restrict__ pos,
    const float* __restrict__ b_con, const float* __restrict__ b_sal,
    const float* __restrict__ b_nov,
    const float* __restrict__ w_cls, const float* __restrict__ b_cls,
    float* __restrict__ out)
{
    int b = blockIdx.x, lane = threadIdx.x;
    float4 s4[8], c4[8];
    const float4* combB = (const float4*)(comb + (size_t)b * H2);
#pragma unroll
    for (int j = 0; j < 8; j++) {
        s4[j] = make_float4(0.f, 0.f, 0.f, 0.f);
        c4[j] = combB[lane * 8 + j];
    }
    float wcls = w_cls[0], bcls = b_cls[0], bnov = b_nov[0];
    float bconst = b_con[0] + b_sal[0];
    const float4* HnB = (const float4*)(Hn + (size_t)b * LL * H2);
    const float4* HoB = (const float4*)(Hout + (size_t)b * LL * H2);

    float4 nhn[8], nho[8];
#pragma unroll
    for (int j = 0; j < 8; j++) {
        nhn[j] = HnB[lane * 8 + j];
        nho[j] = HoB[lane * 8 + j];
    }

    for (int i = 0; i < LL; i++) {
        float4 hn_c[8], ho_c[8];
#pragma unroll
        for (int j = 0; j < 8; j++) { hn_c[j] = nhn[j]; ho_c[j] = nho[j]; }
        if (i + 1 < LL) {
#pragma unroll
            for (int j = 0; j < 8; j++) {
                nhn[j] = HnB[(size_t)(i + 1) * 256 + lane * 8 + j];
                nho[j] = HoB[(size_t)(i + 1) * 256 + lane * 8 + j];
            }
        }

        float pn = 0.f, pb = 0.f;
#pragma unroll
        for (int j = 0; j < 8; j++) {
            pn += hn_c[j].x * s4[j].x + hn_c[j].y * s4[j].y + hn_c[j].z * s4[j].z + hn_c[j].w * s4[j].w;
            pb += ho_c[j].x * c4[j].x + ho_c[j].y * c4[j].y + ho_c[j].z * c4[j].z + ho_c[j].w * c4[j].w;
        }
#pragma unroll
        for (int off = 16; off > 0; off >>= 1) {
            pn += __shfl_xor_sync(0xffffffffu, pn, off);
            pb += __shfl_xor_sync(0xffffffffu, pb, off);
        }
        float base = pb + bconst + pos[i];
        float nov = (i == 0) ? 0.f : (pn + bnov);
        float p = sigm_fast(wcls * (base + nov) + bcls);
#pragma unroll
        for (int j = 0; j < 8; j++) {
            s4[j].x += ho_c[j].x * p; s4[j].y += ho_c[j].y * p;
            s4[j].z += ho_c[j].z * p; s4[j].w += ho_c[j].w * p;
        }
        if (lane == 0) out[b * LL + i] = p;
    }
}

// ---------------- launch --------------------------------------------------------
extern "C" void kernel_launch(void* const* d_in, const int* in_sizes, int n_in,
                              void* d_out, int out_size)
{
    (void)in_sizes; (void)n_in; (void)out_size;
    const float* x     = (const float*)d_in[0];
    const int*   slen  = (const int*)  d_in[1];
    const int*   dlen  = (const int*)  d_in[2];
    const float* Wih_f = (const float*)d_in[3];
    const float* Whh_f = (const float*)d_in[4];
    const float* b_f   = (const float*)d_in[5];
    const float* Wih_b = (const float*)d_in[6];
    const float* Whh_b = (const float*)d_in[7];
    const float* b_b   = (const float*)d_in[8];
    const float* W_doc = (const float*)d_in[9];
    const float* b_doc = (const float*)d_in[10];
    const float* w_con = (const float*)d_in[11];
    const float* b_con = (const float*)d_in[12];
    const float* W_sal = (const float*)d_in[13];
    const float* b_sal = (const float*)d_in[14];
    const float* W_nov = (const float*)d_in[15];
    const float* b_nov = (const float*)d_in[16];
    const float* pos   = (const float*)d_in[17];
    const float* w_cls = (const float*)d_in[18];
    const float* b_cls = (const float*)d_in[19];
    float* out = (float*)d_out;

    float *p_xg0, *p_xg1, *p_Hout, *p_Hn, *p_doc, *p_D, *p_comb;
    __nv_bfloat16 *p_xb, *p_wfB, *p_wbB;
    uint32_t *p_WnT;
    uint4 *p_hb;
    cudaGetSymbolAddress((void**)&p_xg0,  g_xg0);
    cudaGetSymbolAddress((void**)&p_xg1,  g_xg1);
    cudaGetSymbolAddress((void**)&p_Hout, g_Hout);
    cudaGetSymbolAddress((void**)&p_Hn,   g_Hn);
    cudaGetSymbolAddress((void**)&p_xb,   g_xb);
    cudaGetSymbolAddress((void**)&p_wfB,  g_wfB);
    cudaGetSymbolAddress((void**)&p_wbB,  g_wbB);
    cudaGetSymbolAddress((void**)&p_WnT,  g_WnT);
    cudaGetSymbolAddress((void**)&p_hb,   g_hbufb);
    cudaGetSymbolAddress((void**)&p_doc,  g_doc);
    cudaGetSymbolAddress((void**)&p_D,    g_D);
    cudaGetSymbolAddress((void**)&p_comb, g_comb);

    const int M = BB * LL;

    cudaFuncSetAttribute(k_gemm_tf32<false>, cudaFuncAttributeMaxDynamicSharedMemorySize, GEMM_SMEM_BYTES);

    // prep: convert xg-GEMM operands to bf16; W_nov to tf32 transposed
    k_cvtb<<<(M * EE / 4 + 255) / 256, 256>>>(x, p_xb, M * EE / 4);
    k_cvtb<<<(GG * EE / 4 + 255) / 256, 256>>>(Wih_f, p_wfB, GG * EE / 4);
    k_cvtb<<<(GG * EE / 4 + 255) / 256, 256>>>(Wih_b, p_wbB, GG * EE / 4);
    k_transpose<<<dim3(32, 32), dim3(32, 8)>>>(W_nov, p_WnT);

    // both input projections in ONE launch (z selects direction)
    k_gemm_bf16_dual<<<dim3(GG / 128, M / 128, 2), 256>>>(
        p_xb, p_wfB, p_wbB, b_f, b_b, p_xg0, p_xg1, M, GG, EE);

    cudaFuncSetAttribute(k_recurrent, cudaFuncAttributeMaxDynamicSharedMemorySize, REC_SMEM_BYTES);
    k_recurrent<<<128, 256, REC_SMEM_BYTES>>>(Whh_f, Whh_b, slen, dlen,
                                              p_xg0, p_xg1, p_hb, p_Hout, p_doc);

    // D = W_doc . doc + b_doc ; comb = W_sal . D + w_con
    k_mv<<<dim3(H2 / 8, BB), 256>>>(W_doc, p_doc, b_doc, p_D);
    k_mv<<<dim3(H2 / 8, BB), 256>>>(W_sal, p_D, w_con, p_comb);

    // novelty GEMM stays tf32 (feeds output scores directly)
    k_gemm_tf32<false><<<dim3(H2 / 128, M / 128), 256, GEMM_SMEM_BYTES>>>((const uint32_t*)p_Hout, p_WnT, nullptr, p_Hn, M, H2, H2);

    k_scan<<<BB, 32>>>(p_Hout, p_Hn, p_comb, pos, b_con, b_sal, b_nov, w_cls, b_cls, out);
}

// round 17
// speedup vs baseline: 1.1052x; 1.0327x over previous
#include <cuda_runtime.h>
#include <cuda_bf16.h>
#include <math.h>
#include <stdint.h>

#define BB 64
#define LL 256
#define EE 512
#define HH 512
#define GG 2048   // 4*H
#define H2 1024   // 2*H
#define ZP 132    // s_z row stride (floats)

// ---------------- scratch (device globals; no allocations allowed) -------------
__device__ float g_xg0[LL * BB * GG];
__device__ float g_xg1[LL * BB * GG];
__device__ float g_Hout[BB * LL * H2];           // tf32 bit patterns (valid fp32)
__device__ float g_Hn[BB * LL * H2];
__device__ __nv_bfloat16 g_xb[BB * LL * EE];     // x bf16
__device__ __nv_bfloat16 g_wfB[GG * EE];         // Wih_f bf16
__device__ __nv_bfloat16 g_wbB[GG * EE];         // Wih_b bf16
__device__ uint32_t g_WnT[H2 * H2];              // W_nov transposed, tf32
__device__ uint4 g_hbufb[8 * 1024];              // bf16 fragment-major h per (dir,bg4)
__device__ float g_doc[BB * H2];
__device__ float g_D[BB * H2];
__device__ float g_comb[BB * H2];
__device__ unsigned g_cnt[8 * 32];               // init barrier (atomic, replay-safe)
__device__ unsigned g_gen[8 * 32];
__device__ unsigned g_flag[8 * 16 * 32];         // step flags, 128B apart

// ---------------- init barrier (16 CTAs/group, atomicInc wraps) ----------------
__device__ __forceinline__ void gsync_grp(int grp) {
    __syncthreads();
    if (threadIdx.x == 0) {
        __threadfence();
        volatile unsigned* gen = &g_gen[grp * 32];
        unsigned old = *gen;
        if (atomicInc(&g_cnt[grp * 32], 15u) == 15u) {
            atomicAdd(&g_gen[grp * 32], 1u);
        } else {
            while (*gen == old) __nanosleep(32);
        }
    }
    __syncthreads();
}

__device__ __forceinline__ float tanha(float x) {
    float r; asm("tanh.approx.f32 %0, %1;" : "=f"(r) : "f"(x)); return r;
}
__device__ __forceinline__ float sigm_fast(float x) {
    return fmaf(tanha(0.5f * x), 0.5f, 0.5f);
}
__device__ __forceinline__ uint32_t f2tf(float f) {
    uint32_t u; asm("cvt.rna.tf32.f32 %0, %1;" : "=r"(u) : "f"(f)); return u;
}
__device__ __forceinline__ void mma_tf32(float* c, const uint32_t* a, const uint32_t* b) {
    asm volatile(
        "mma.sync.aligned.m16n8k8.row.col.f32.tf32.tf32.f32 "
        "{%0,%1,%2,%3}, {%4,%5,%6,%7}, {%8,%9}, {%0,%1,%2,%3};"
        : "+f"(c[0]), "+f"(c[1]), "+f"(c[2]), "+f"(c[3])
        : "r"(a[0]), "r"(a[1]), "r"(a[2]), "r"(a[3]), "r"(b[0]), "r"(b[1]));
}
__device__ __forceinline__ void mma_bf16(float* c, const uint32_t* a, const uint32_t* b) {
    asm volatile(
        "mma.sync.aligned.m16n8k16.row.col.f32.bf16.bf16.f32 "
        "{%0,%1,%2,%3}, {%4,%5,%6,%7}, {%8,%9}, {%0,%1,%2,%3};"
        : "+f"(c[0]), "+f"(c[1]), "+f"(c[2]), "+f"(c[3])
        : "r"(a[0]), "r"(a[1]), "r"(a[2]), "r"(a[3]), "r"(b[0]), "r"(b[1]));
}
__device__ __forceinline__ uint32_t smem_u32(const void* p) {
    uint32_t a;
    asm("{.reg .u64 t; cvta.to.shared.u64 t, %1; cvt.u32.u64 %0, t;}" : "=r"(a) : "l"(p));
    return a;
}
#define CP_ASYNC16(dst, src) \
    asm volatile("cp.async.ca.shared.global [%0], [%1], 16;" :: "r"(dst), "l"(src))
#define CP_ASYNC16_CG(dst, src) \
    asm volatile("cp.async.cg.shared.global [%0], [%1], 16;" :: "r"(dst), "l"(src))
#define CP_COMMIT() asm volatile("cp.async.commit_group;")
#define CP_WAIT(n)  asm volatile("cp.async.wait_group %0;" :: "n"(n))

#define GEMM_SMEM_BYTES (4 * 128 * 36 * 4)    // tf32 gemm dynamic smem (73728)
// recurrent smem: h(16KB) + Wpack(128KB) + z(16*132*4) + c(2KB)
#define REC_SMEM_BYTES (1024 * 16 + 8192 * 16 + 16 * ZP * 4 + 512 * 4)
#define BROW 40   // bf16 gemm smem row stride in bf16 units (80 bytes, conflict-free)

// ---------------- elementwise fp32 -> bf16 (rn) --------------------------------
__global__ void k_cvtb(const float* __restrict__ in, __nv_bfloat16* __restrict__ out, int n4) {
    int i = blockIdx.x * blockDim.x + threadIdx.x;
    if (i < n4) {
        float4 v = ((const float4*)in)[i];
        __nv_bfloat162 lo = __floats2bfloat162_rn(v.x, v.y);
        __nv_bfloat162 hi = __floats2bfloat162_rn(v.z, v.w);
        uint2 o = make_uint2(*(uint32_t*)&lo, *(uint32_t*)&hi);
        ((uint2*)out)[i] = o;
    }
}

// ---------------- bf16 GEMM (m16n8k16), cp.async dbuf, dual-output via z -------
__global__ __launch_bounds__(256, 2) void k_gemm_bf16_dual(
    const __nv_bfloat16* __restrict__ A,
    const __nv_bfloat16* __restrict__ Bt0, const __nv_bfloat16* __restrict__ Bt1,
    const float* __restrict__ bias0, const float* __restrict__ bias1,
    float* __restrict__ C0, float* __restrict__ C1,
    int M, int N, int K)
{
    __shared__ __nv_bfloat16 Asm[2][128 * BROW];
    __shared__ __nv_bfloat16 Bsm[2][128 * BROW];
    const __nv_bfloat16* Bt = blockIdx.z ? Bt1 : Bt0;
    const float* bias = blockIdx.z ? bias1 : bias0;
    float* C = blockIdx.z ? C1 : C0;

    const int tid = threadIdx.x;
    const int lane = tid & 31;
    const int warp = tid >> 5;
    const int wm = warp >> 2;
    const int wn = warp & 3;
    const int g  = lane >> 2;
    const int tg = lane & 3;
    const int bm = blockIdx.y * 128;
    const int bn = blockIdx.x * 128;
    const int srow = tid >> 2;
    const int sc   = (tid & 3) * 8;

    const uint32_t as_base = smem_u32(&Asm[0][0]);
    const uint32_t bs_base = smem_u32(&Bsm[0][0]);
    const uint32_t soff = (srow * BROW + sc) * 2;
    const uint32_t rstep = 64 * BROW * 2;
    const uint32_t bufstep = 128 * BROW * 2;

    float acc[4][4][4];
#pragma unroll
    for (int i = 0; i < 4; i++)
#pragma unroll
        for (int j = 0; j < 4; j++)
#pragma unroll
            for (int e = 0; e < 4; e++) acc[i][j][e] = 0.f;

    const int ntiles = K >> 5;

#pragma unroll
    for (int r = 0; r < 2; r++) {
        int row = srow + 64 * r;
        CP_ASYNC16(as_base + soff + r * rstep, A + (size_t)(bm + row) * K + sc);
        CP_ASYNC16(bs_base + soff + r * rstep, Bt + (size_t)(bn + row) * K + sc);
    }
    CP_COMMIT();

    for (int kt = 0; kt < ntiles; kt++) {
        const int buf = kt & 1;
        if (kt + 1 < ntiles) {
            const int k0n = (kt + 1) << 5;
            const uint32_t bofs = (buf ^ 1) * bufstep;
#pragma unroll
            for (int r = 0; r < 2; r++) {
                int row = srow + 64 * r;
                CP_ASYNC16(as_base + bofs + soff + r * rstep, A + (size_t)(bm + row) * K + k0n + sc);
                CP_ASYNC16(bs_base + bofs + soff + r * rstep, Bt + (size_t)(bn + row) * K + k0n + sc);
            }
            CP_COMMIT();
            CP_WAIT(1);
        } else {
            CP_WAIT(0);
        }
        __syncthreads();

        const __nv_bfloat16* Ab = Asm[buf];
        const __nv_bfloat16* Bb = Bsm[buf];
#pragma unroll
        for (int kk = 0; kk < 2; kk++) {
            const int kc = kk * 16;
            uint32_t a[4][4], b[4][2];
#pragma unroll
            for (int i = 0; i < 4; i++) {
                int r0 = wm * 64 + i * 16 + g;
                a[i][0] = *(const uint32_t*)&Ab[r0 * BROW + kc + 2 * tg];
                a[i][1] = *(const uint32_t*)&Ab[(r0 + 8) * BROW + kc + 2 * tg];
                a[i][2] = *(const uint32_t*)&Ab[r0 * BROW + kc + 8 + 2 * tg];
                a[i][3] = *(const uint32_t*)&Ab[(r0 + 8) * BROW + kc + 8 + 2 * tg];
            }
#pragma unroll
            for (int j = 0; j < 4; j++) {
                int n0 = wn * 32 + j * 8 + g;
                b[j][0] = *(const uint32_t*)&Bb[n0 * BROW + kc + 2 * tg];
                b[j][1] = *(const uint32_t*)&Bb[n0 * BROW + kc + 8 + 2 * tg];
            }
#pragma unroll
            for (int i = 0; i < 4; i++)
#pragma unroll
                for (int j = 0; j < 4; j++) mma_bf16(acc[i][j], a[i], b[j]);
        }
        __syncthreads();
    }
#pragma unroll
    for (int i = 0; i < 4; i++) {
#pragma unroll
        for (int j = 0; j < 4; j++) {
            int col = bn + wn * 32 + j * 8 + tg * 2;
            float bv0 = bias[col];
            float bv1 = bias[col + 1];
            int m0 = bm + wm * 64 + i * 16 + g;
            int m1 = m0 + 8;
            int r0 = (m0 & (LL - 1)) * BB + (m0 >> 8);   // REMAP
            int r1 = (m1 & (LL - 1)) * BB + (m1 >> 8);
            *(float2*)(C + (size_t)r0 * N + col) = make_float2(acc[i][j][0] + bv0, acc[i][j][1] + bv1);
            *(float2*)(C + (size_t)r1 * N + col) = make_float2(acc[i][j][2] + bv0, acc[i][j][3] + bv1);
        }
    }
}

// ---------------- tf32 GEMM (novelty), cp.async double-buffer (R9-validated) ---
template <bool REMAP>
__global__ __launch_bounds__(256, 2) void k_gemm_tf32(
    const uint32_t* __restrict__ A, const uint32_t* __restrict__ Bt,
    const float* __restrict__ bias, float* __restrict__ C,
    int M, int N, int K)
{
    extern __shared__ uint32_t smg[];
    uint32_t* Asm = smg;
    uint32_t* Bsm = smg + 2 * 128 * 36;
    const int tid = threadIdx.x;
    const int lane = tid & 31;
    const int warp = tid >> 5;
    const int wm = warp >> 2;
    const int wn = warp & 3;
    const int g  = lane >> 2;
    const int tg = lane & 3;
    const int bm = blockIdx.y * 128;
    const int bn = blockIdx.x * 128;
    const int srow = tid >> 3;
    const int scol = (tid & 7) << 2;

    const uint32_t as_base = smem_u32(Asm);
    const uint32_t bs_base = smem_u32(Bsm);
    const uint32_t soff = (srow * 36 + scol) * 4;

    float acc[4][4][4];
#pragma unroll
    for (int i = 0; i < 4; i++)
#pragma unroll
        for (int j = 0; j < 4; j++)
#pragma unroll
            for (int e = 0; e < 4; e++) acc[i][j][e] = 0.f;

    const int ntiles = K >> 5;

#pragma unroll
    for (int r = 0; r < 4; r++) {
        int row = srow + 32 * r;
        CP_ASYNC16(as_base + soff + r * (32 * 36 * 4), A + (size_t)(bm + row) * K + scol);
        CP_ASYNC16(bs_base + soff + r * (32 * 36 * 4), Bt + (size_t)(bn + row) * K + scol);
    }
    CP_COMMIT();

    for (int kt = 0; kt < ntiles; kt++) {
        const int buf = kt & 1;
        if (kt + 1 < ntiles) {
            const int k0n = (kt + 1) << 5;
            const uint32_t bofs = (buf ^ 1) * (128 * 36 * 4);
#pragma unroll
            for (int r = 0; r < 4; r++) {
                int row = srow + 32 * r;
                CP_ASYNC16(as_base + bofs + soff + r * (32 * 36 * 4), A + (size_t)(bm + row) * K + k0n + scol);
                CP_ASYNC16(bs_base + bofs + soff + r * (32 * 36 * 4), Bt + (size_t)(bn + row) * K + k0n + scol);
            }
            CP_COMMIT();
            CP_WAIT(1);
        } else {
            CP_WAIT(0);
        }
        __syncthreads();

        const uint32_t* Ab = Asm + buf * (128 * 36);
        const uint32_t* Bb = Bsm + buf * (128 * 36);
#pragma unroll
        for (int kk = 0; kk < 32; kk += 8) {
            uint32_t a[4][4], b[4][2];
#pragma unroll
            for (int i = 0; i < 4; i++) {
                int base = wm * 64 + i * 16;
                a[i][0] = Ab[(base + g)     * 36 + kk + tg];
                a[i][1] = Ab[(base + g + 8) * 36 + kk + tg];
                a[i][2] = Ab[(base + g)     * 36 + kk + tg + 4];
                a[i][3] = Ab[(base + g + 8) * 36 + kk + tg + 4];
            }
#pragma unroll
            for (int j = 0; j < 4; j++) {
                int nb = wn * 32 + j * 8;
                b[j][0] = Bb[(nb + g) * 36 + kk + tg];
                b[j][1] = Bb[(nb + g) * 36 + kk + tg + 4];
            }
#pragma unroll
            for (int i = 0; i < 4; i++)
#pragma unroll
                for (int j = 0; j < 4; j++) mma_tf32(acc[i][j], a[i], b[j]);
        }
        __syncthreads();
    }
#pragma unroll
    for (int i = 0; i < 4; i++) {
#pragma unroll
        for (int j = 0; j < 4; j++) {
            int col = bn + wn * 32 + j * 8 + tg * 2;
            float bv0 = bias ? bias[col] : 0.f;
            float bv1 = bias ? bias[col + 1] : 0.f;
            int m0 = bm + wm * 64 + i * 16 + g;
            int m1 = m0 + 8;
            int r0 = REMAP ? ((m0 & (LL - 1)) * BB + (m0 >> 8)) : m0;
            int r1 = REMAP ? ((m1 & (LL - 1)) * BB + (m1 >> 8)) : m1;
            *(float2*)(C + (size_t)r0 * N + col) = make_float2(acc[i][j][0] + bv0, acc[i][j][1] + bv1);
            *(float2*)(C + (size_t)r1 * N + col) = make_float2(acc[i][j][2] + bv0, acc[i][j][3] + bv1);
        }
    }
}

// ---------------- 1024x1024 transpose, fp32 -> tf32 bits ------------------------
__global__ void k_transpose(const float* __restrict__ in, uint32_t* __restrict__ out) {
    __shared__ float t[32][33];
    int bx = blockIdx.x * 32, by = blockIdx.y * 32;
    int x = threadIdx.x, y = threadIdx.y;
#pragma unroll
    for (int j = 0; j < 32; j += 8) t[y + j][x] = in[(size_t)(by + y + j) * H2 + bx + x];
    __syncthreads();
#pragma unroll
    for (int j = 0; j < 32; j += 8) out[(size_t)(bx + y + j) * H2 + by + x] = f2tf(t[x][y + j]);
}

// ---------------- persistent bidirectional LSTM, bf16 mma ----------------------
// 128 CTAs = (dir, bg in 0..3, useg in 0..15): 16 batch rows x 32 units x 4 gates.
// z[16,128] = h[16,512] @ W[128,512]^T.  Groups of 16 CTAs share (dir,bg).
// Whh fragments register-resident; h global layout [kk 32][lane 32] uint4 / group.
__global__ __launch_bounds__(256, 1) void k_recurrent(
    const float* __restrict__ Whh_f, const float* __restrict__ Whh_b,
    const int* __restrict__ slen, const int* __restrict__ dlen,
    const float* __restrict__ xg0, const float* __restrict__ xg1,
    uint4* __restrict__ hb, float* __restrict__ Hout, float* __restrict__ doc)
{
    extern __shared__ float sm[];
    uint4* s_h4  = (uint4*)sm;                   // 1024 uint4 (16KB)
    uint4* s_wb4 = (uint4*)sm + 1024;            // [warp 8][kk 32][lane 32] (128KB), staging
    float* s_z = sm + (1024 + 8192) * 4;         // [16][ZP]
    float* s_c = s_z + 16 * ZP;                  // [512]

    const int tid = threadIdx.x;
    const int lane = tid & 31;
    const int warp = tid >> 5;
    const int g  = lane >> 2;
    const int tg = lane & 3;
    const int dir  = blockIdx.x >> 6;
    const int bg   = (blockIdx.x >> 4) & 3;
    const int useg = blockIdx.x & 15;
    const int hu0  = useg * 32;
    const int b0   = bg * 16;
    const int grp  = blockIdx.x >> 4;            // dir*4 + bg
    const int cta  = blockIdx.x & 15;
    const float* Whh = dir ? Whh_b : Whh_f;
    const float* xg  = dir ? xg1 : xg0;
    uint4* hperm = hb + grp * 1024;

    if (tid == 0) g_flag[grp * 512 + cta * 32] = 0u;

    // one-time: pack Whh fragments bf16 [warp][kk][lane] uint4 = (j0k0,j0k1,j1k0,j1k1)
    uint32_t* s_ww = (uint32_t*)s_wb4;
    for (int w = tid; w < 32768; w += 256) {
        int comp = w & 3;
        int l    = (w >> 2) & 31;
        int kk   = (w >> 7) & 31;
        int wp   = w >> 12;
        int j   = comp >> 1;
        int khi = comp & 1;
        int n = wp * 16 + j * 8 + (l >> 2);      // local gate-col 0..127
        int k = kk * 16 + khi * 8 + (l & 3) * 2;
        int gate = n >> 5, unit = hu0 + (n & 31);
        const float* wr = Whh + (size_t)(gate * HH + unit) * HH + k;
        __nv_bfloat162 p = __floats2bfloat162_rn(wr[0], wr[1]);
        s_ww[w] = *(uint32_t*)&p;
    }
    for (int i = tid; i < 512; i += 256) s_c[i] = 0.f;

    // per-thread gate-element mapping (bl = local batch row, u = local unit)
    int pofs[2], bidx[2], huv[2];
    __nv_bfloat16* hpw = (__nv_bfloat16*)hperm;
#pragma unroll
    for (int half = 0; half < 2; half++) {
        int idx = tid + half * 256;
        int bl = idx >> 5, u = idx & 31;
        int hu = hu0 + u;
        int kk = hu >> 4, km = hu & 15;
        int u4i = kk * 32 + (bl & 7) * 4 + ((km & 7) >> 1);
        int comp = (bl >> 3) + 2 * (km >> 3);
        pofs[half] = u4i * 8 + comp * 2 + (km & 1);
        bidx[half] = b0 + bl;
        huv[half]  = hu;
        hpw[pofs[half]] = __float2bfloat16(0.f);
    }
    __syncthreads();

    // hoist this thread's Whh fragments into registers (loop-invariant)
    const uint4* bwp = s_wb4 + warp * 1024 + lane;
    uint4 b_reg[32];
#pragma unroll
    for (int kk = 0; kk < 32; kk++) b_reg[kk] = bwp[kk * 32];

    gsync_grp(grp);

    const int sl0 = slen[b0 + (tid >> 5)];
    const int sl1 = slen[b0 + 8 + (tid >> 5)];
    const int dl0 = dlen[b0 + (tid >> 5)];
    const int dl1 = dlen[b0 + 8 + (tid >> 5)];
    float docacc[2] = {0.f, 0.f};

    const uint4* awp = s_h4 + lane;              // same A rows for all warps
    const uint4* hsrc4 = (const uint4*)hperm;
    const uint32_t hb_base = smem_u32(s_h4);

    for (int step = 0; step < LL; ++step) {
        const int t = dir ? (LL - 1 - step) : step;

        // stage group's h block (16KB) via cp.async
#pragma unroll
        for (int r = 0; r < 4; r++) {
            int i = tid + r * 256;
            CP_ASYNC16_CG(hb_base + i * 16, hsrc4 + i);
        }
        CP_COMMIT();

        // prefetch xg for both halves (overlaps cp.async)
        float x0[4], x1[4];
        {
            const float* xp0 = xg + ((size_t)t * BB + bidx[0]) * GG + huv[0];
            x0[0] = xp0[0]; x0[1] = xp0[HH]; x0[2] = xp0[2 * HH]; x0[3] = xp0[3 * HH];
            const float* xp1 = xg + ((size_t)t * BB + bidx[1]) * GG + huv[1];
            x1[0] = xp1[0]; x1[1] = xp1[HH]; x1[2] = xp1[2 * HH]; x1[3] = xp1[3 * HH];
        }

        CP_WAIT(0);
        __syncthreads();

        float acc0[4] = {0.f, 0.f, 0.f, 0.f};
        float acc1[4] = {0.f, 0.f, 0.f, 0.f};
#pragma unroll
        for (int kk = 0; kk < 32; kk++) {
            uint4 a4 = awp[kk * 32];
            uint32_t b0r[2] = {b_reg[kk].x, b_reg[kk].y};
            uint32_t b1r[2] = {b_reg[kk].z, b_reg[kk].w};
            mma_bf16(acc0, (const uint32_t*)&a4, b0r);
            mma_bf16(acc1, (const uint32_t*)&a4, b1r);
        }
        {
            int zc = warp * 16 + tg * 2;
            *(float2*)&s_z[g * ZP + zc]           = make_float2(acc0[0], acc0[1]);
            *(float2*)&s_z[(g + 8) * ZP + zc]     = make_float2(acc0[2], acc0[3]);
            *(float2*)&s_z[g * ZP + zc + 8]       = make_float2(acc1[0], acc1[1]);
            *(float2*)&s_z[(g + 8) * ZP + zc + 8] = make_float2(acc1[2], acc1[3]);
        }
        __syncthreads();

        // gates: compute, write h (and cell) only; stash Hout value
        float hv[2]; bool av[2];
#pragma unroll
        for (int half = 0; half < 2; half++) {
            int idx = tid + half * 256;
            int bl = idx >> 5, u = idx & 31;
            const float* xv = half ? x1 : x0;
            float zi = s_z[bl * ZP + u]      + xv[0];
            float zf = s_z[bl * ZP + 32 + u] + xv[1];
            float zg = s_z[bl * ZP + 64 + u] + xv[2];
            float zo = s_z[bl * ZP + 96 + u] + xv[3];
            float c  = s_c[idx];
            float cn = sigm_fast(zf) * c + sigm_fast(zi) * tanha(zg);
            float hn = sigm_fast(zo) * tanha(cn);
            bool act = t < (half ? sl1 : sl0);
            if (act) {
                s_c[idx] = cn;
                hpw[pofs[half]] = __float2bfloat16(hn);
            }
            hv[half] = hn; av[half] = act;
        }

        // arrive early: only h writeback must be visible before the flag
        __syncthreads();
        if (tid == 0) {
            __threadfence();
            atomicExch(&g_flag[grp * 512 + cta * 32], (unsigned)step + 1u);
        }

        // Hout + doc accumulate while peers arrive
#pragma unroll
        for (int half = 0; half < 2; half++) {
            int b = bidx[half];
            float o = av[half] ? hv[half] : 0.f;
            Hout[(size_t)(b * LL + t) * H2 + dir * HH + huv[half]] =
                av[half] ? __uint_as_float(f2tf(hv[half])) : 0.f;
            if (t < (half ? dl1 : dl0)) docacc[half] += o;
        }

        if (tid < 16) {
            const volatile unsigned* fl = &g_flag[grp * 512];
            unsigned tgt = (unsigned)step + 1u;
            while (fl[tid * 32] < tgt) __nanosleep(16);
        }
        __syncthreads();
    }

#pragma unroll
    for (int half = 0; half < 2; half++) {
        float inv = 1.f / (float)(half ? dl1 : dl0);
        doc[bidx[half] * H2 + dir * HH + huv[half]] = docacc[half] * inv;
    }
}

// ---------------- epilogue -----------------------------------------------------
__global__ void k_mv(const float* __restrict__ W, const float* __restrict__ v,
                     const float* __restrict__ bias, float* __restrict__ out)
{
    int b = blockIdx.y;
    int wid = threadIdx.x >> 5, lane = threadIdx.x & 31;
    int d = blockIdx.x * 8 + wid;
    const float4* wp = (const float4*)(W + (size_t)d * H2);
    const float4* vp = (const float4*)(v + (size_t)b * H2);
    float acc = 0.f;
    for (int e = lane; e < H2 / 4; e += 32) {
        float4 a = wp[e], c = vp[e];
        acc += a.x * c.x + a.y * c.y + a.z * c.z + a.w * c.w;
    }
#pragma unroll
    for (int off = 16; off > 0; off >>= 1) acc += __shfl_down_sync(0xffffffffu, acc, off);
    if (lane == 0) out[b * H2 + d] = acc + (bias ? bias[d] : 0.f);
}

// sequential scan; 1 warp per batch; both Hn and Hout prefetched one step ahead
__global__ __launch_bounds__(32) void k_scan(
    const float* __restrict__ Hout, const float* __restrict__ Hn,
    const float* __restrict__ comb, const float* __restrict__ pos,
    const float* __restrict__ b_con, const float* __restrict__ b_sal,
    const float* __restrict__ b_nov,
    const float* __restrict__ w_cls, const float* __restrict__ b_cls,
    float* __restrict__ out)
{
    int b = blockIdx.x, lane = threadIdx.x;
    float4 s4[8], c4[8];
    const float4* combB = (const float4*)(comb + (size_t)b * H2);
#pragma unroll
    for (int j = 0; j < 8; j++) {
        s4[j] = make_float4(0.f, 0.f, 0.f, 0.f);
        c4[j] = combB[lane * 8 + j];
    }
    float wcls = w_cls[0], bcls = b_cls[0], bnov = b_nov[0];
    float bconst = b_con[0] + b_sal[0];
    const float4* HnB = (const float4*)(Hn + (size_t)b * LL * H2);
    const float4* HoB = (const float4*)(Hout + (size_t)b * LL * H2);

    float4 nhn[8], nho[8];
#pragma unroll
    for (int j = 0; j < 8; j++) {
        nhn[j] = HnB[lane * 8 + j];
        nho[j] = HoB[lane * 8 + j];
    }

    for (int i = 0; i < LL; i++) {
        float4 hn_c[8], ho_c[8];
#pragma unroll
        for (int j = 0; j < 8; j++) { hn_c[j] = nhn[j]; ho_c[j] = nho[j]; }
        if (i + 1 < LL) {
#pragma unroll
            for (int j = 0; j < 8; j++) {
                nhn[j] = HnB[(size_t)(i + 1) * 256 + lane * 8 + j];
                nho[j] = HoB[(size_t)(i + 1) * 256 + lane * 8 + j];
            }
        }

        float pn = 0.f, pb = 0.f;
#pragma unroll
        for (int j = 0; j < 8; j++) {
            pn += hn_c[j].x * s4[j].x + hn_c[j].y * s4[j].y + hn_c[j].z * s4[j].z + hn_c[j].w * s4[j].w;
            pb += ho_c[j].x * c4[j].x + ho_c[j].y * c4[j].y + ho_c[j].z * c4[j].z + ho_c[j].w * c4[j].w;
        }
#pragma unroll
        for (int off = 16; off > 0; off >>= 1) {
            pn += __shfl_xor_sync(0xffffffffu, pn, off);
            pb += __shfl_xor_sync(0xffffffffu, pb, off);
        }
        float base = pb + bconst + pos[i];
        float nov = (i == 0) ? 0.f : (pn + bnov);
        float p = sigm_fast(wcls * (base + nov) + bcls);
#pragma unroll
        for (int j = 0; j < 8; j++) {
            s4[j].x += ho_c[j].x * p; s4[j].y += ho_c[j].y * p;
            s4[j].z += ho_c[j].z * p; s4[j].w += ho_c[j].w * p;
        }
        if (lane == 0) out[b * LL + i] = p;
    }
}

// ---------------- launch --------------------------------------------------------
extern "C" void kernel_launch(void* const* d_in, const int* in_sizes, int n_in,
                              void* d_out, int out_size)
{
    (void)in_sizes; (void)n_in; (void)out_size;
    const float* x     = (const float*)d_in[0];
    const int*   slen  = (const int*)  d_in[1];
    const int*   dlen  = (const int*)  d_in[2];
    const float* Wih_f = (const float*)d_in[3];
    const float* Whh_f = (const float*)d_in[4];
    const float* b_f   = (const float*)d_in[5];
    const float* Wih_b = (const float*)d_in[6];
    const float* Whh_b = (const float*)d_in[7];
    const float* b_b   = (const float*)d_in[8];
    const float* W_doc = (const float*)d_in[9];
    const float* b_doc = (const float*)d_in[10];
    const float* w_con = (const float*)d_in[11];
    const float* b_con = (const float*)d_in[12];
    const float* W_sal = (const float*)d_in[13];
    const float* b_sal = (const float*)d_in[14];
    const float* W_nov = (const float*)d_in[15];
    const float* b_nov = (const float*)d_in[16];
    const float* pos   = (const float*)d_in[17];
    const float* w_cls = (const float*)d_in[18];
    const float* b_cls = (const float*)d_in[19];
    float* out = (float*)d_out;

    float *p_xg0, *p_xg1, *p_Hout, *p_Hn, *p_doc, *p_D, *p_comb;
    __nv_bfloat16 *p_xb, *p_wfB, *p_wbB;
    uint32_t *p_WnT;
    uint4 *p_hb;
    cudaGetSymbolAddress((void**)&p_xg0,  g_xg0);
    cudaGetSymbolAddress((void**)&p_xg1,  g_xg1);
    cudaGetSymbolAddress((void**)&p_Hout, g_Hout);
    cudaGetSymbolAddress((void**)&p_Hn,   g_Hn);
    cudaGetSymbolAddress((void**)&p_xb,   g_xb);
    cudaGetSymbolAddress((void**)&p_wfB,  g_wfB);
    cudaGetSymbolAddress((void**)&p_wbB,  g_wbB);
    cudaGetSymbolAddress((void**)&p_WnT,  g_WnT);
    cudaGetSymbolAddress((void**)&p_hb,   g_hbufb);
    cudaGetSymbolAddress((void**)&p_doc,  g_doc);
    cudaGetSymbolAddress((void**)&p_D,    g_D);
    cudaGetSymbolAddress((void**)&p_comb, g_comb);

    const int M = BB * LL;

    cudaFuncSetAttribute(k_gemm_tf32<false>, cudaFuncAttributeMaxDynamicSharedMemorySize, GEMM_SMEM_BYTES);

    // prep: convert xg-GEMM operands to bf16; W_nov to tf32 transposed
    k_cvtb<<<(M * EE / 4 + 255) / 256, 256>>>(x, p_xb, M * EE / 4);
    k_cvtb<<<(GG * EE / 4 + 255) / 256, 256>>>(Wih_f, p_wfB, GG * EE / 4);
    k_cvtb<<<(GG * EE / 4 + 255) / 256, 256>>>(Wih_b, p_wbB, GG * EE / 4);
    k_transpose<<<dim3(32, 32), dim3(32, 8)>>>(W_nov, p_WnT);

    // both input projections in ONE launch (z selects direction)
    k_gemm_bf16_dual<<<dim3(GG / 128, M / 128, 2), 256>>>(
        p_xb, p_wfB, p_wbB, b_f, b_b, p_xg0, p_xg1, M, GG, EE);

    cudaFuncSetAttribute(k_recurrent, cudaFuncAttributeMaxDynamicSharedMemorySize, REC_SMEM_BYTES);
    k_recurrent<<<128, 256, REC_SMEM_BYTES>>>(Whh_f, Whh_b, slen, dlen,
                                              p_xg0, p_xg1, p_hb, p_Hout, p_doc);

    // D = W_doc . doc + b_doc ; comb = W_sal . D + w_con
    k_mv<<<dim3(H2 / 8, BB), 256>>>(W_doc, p_doc, b_doc, p_D);
    k_mv<<<dim3(H2 / 8, BB), 256>>>(W_sal, p_D, w_con, p_comb);

    // novelty GEMM stays tf32 (feeds output scores directly)
    k_gemm_tf32<false><<<dim3(H2 / 128, M / 128), 256, GEMM_SMEM_BYTES>>>((const uint32_t*)p_Hout, p_WnT, nullptr, p_Hn, M, H2, H2);

    k_scan<<<BB, 32>>>(p_Hout, p_Hn, p_comb, pos, b_con, b_sal, b_nov, w_cls, b_cls, out);
}